// round 1
// baseline (speedup 1.0000x reference)
#include <cuda_runtime.h>
#include <math.h>

// Problem shapes (fixed by the dataset)
#define BSZ   8
#define LSEQ  4096
#define HDIM  512
#define PDIM  256
#define MROWS (BSZ*LSEQ)     // 32768
#define KD    512            // inner dim for both GEMMs (H, and 2P)
#define ND    512            // outer dim for both GEMMs (2P, and H)
#define LC    128            // scan chunk length
#define NCH   (LSEQ/LC)      // 32 chunks per sequence

// ---------------- device scratch (static; no runtime allocation) ----------------
__device__ float2 g_Bu[(size_t)MROWS * PDIM];   // 64 MB: Bu, then xs in-place
__device__ float2 g_lambda[PDIM];               // λ
__device__ float2 g_lampow[PDIM];               // λ^LC
__device__ float2 g_f[PDIM];                    // (λ-1)/Λ
__device__ float  g_W1[ND * KD];                // [2P][H]
__device__ float  g_W2[HDIM * KD];              // [H][2P]
__device__ float2 g_carry[BSZ * NCH * PDIM];    // chunk-final states
__device__ float2 g_carry_in[BSZ * NCH * PDIM]; // incoming carries per chunk

// complex state update: s' = lam*s + u
__device__ __forceinline__ float2 cfma(float2 l, float2 s, float2 u) {
    float2 r;
    r.x = fmaf(l.x, s.x, fmaf(-l.y, s.y, u.x));
    r.y = fmaf(l.x, s.y, fmaf( l.y, s.x, u.y));
    return r;
}

// ---------------- precompute kernels ----------------
__global__ void prep_params(const float* __restrict__ Lre,
                            const float* __restrict__ Lim,
                            const float* __restrict__ lstep) {
    int p = threadIdx.x;
    float step = expf(lstep[p]);
    // arguments rounded to fp32 exactly like the reference, trig in double for accuracy
    float ar = Lre[p] * step;
    float ai = Lim[p] * step;
    double mag = exp((double)ar);
    float2 lam;
    lam.x = (float)(mag * cos((double)ai));
    lam.y = (float)(mag * sin((double)ai));
    g_lambda[p] = lam;
    // lam^LC (LC = 128 = 2^7) via repeated squaring in double
    double zr = lam.x, zi = lam.y;
    #pragma unroll
    for (int i = 0; i < 7; i++) {
        double nr = zr*zr - zi*zi;
        double ni = 2.0*zr*zi;
        zr = nr; zi = ni;
    }
    g_lampow[p] = make_float2((float)zr, (float)zi);
    // f = (lam - 1) / Lambda   (complex division)
    float lr = Lre[p], li = Lim[p];
    float nr = lam.x - 1.0f, ni = lam.y;
    float den = lr*lr + li*li;
    g_f[p] = make_float2((nr*lr + ni*li)/den, (ni*lr - nr*li)/den);
}

__global__ void prep_w1(const float* __restrict__ Bm) {  // B: (P,H,2)
    int idx = blockIdx.x * blockDim.x + threadIdx.x;     // over P*H
    int p = idx / HDIM, h = idx % HDIM;
    float2 f = g_f[p];
    float b0 = Bm[(size_t)(p*HDIM + h)*2 + 0];
    float b1 = Bm[(size_t)(p*HDIM + h)*2 + 1];
    g_W1[(size_t)(2*p    )*HDIM + h] = f.x*b0 - f.y*b1;  // Re(f * B~)
    g_W1[(size_t)(2*p + 1)*HDIM + h] = f.x*b1 + f.y*b0;  // Im(f * B~)
}

__global__ void prep_w2(const float* __restrict__ Cm) {  // C: (H,P,2)
    int idx = blockIdx.x * blockDim.x + threadIdx.x;     // over H*P
    int h = idx / PDIM, p = idx % PDIM;
    g_W2[(size_t)h*KD + 2*p    ] =  2.0f * Cm[(size_t)(h*PDIM + p)*2 + 0];
    g_W2[(size_t)h*KD + 2*p + 1] = -2.0f * Cm[(size_t)(h*PDIM + p)*2 + 1];
}

// ---------------- SGEMM: out[m][n] = sum_k A[m][k] * W[n][k]  (+ epilogue) ----------------
// BM=BN=128, BK=16, 256 threads, 8x8 per thread (4+4 split to avoid smem conflicts)
template<int EPI>
__global__ __launch_bounds__(256)
void sgemm(const float* __restrict__ A, const float* __restrict__ W,
           float* __restrict__ out, const float* __restrict__ Dv,
           const float* __restrict__ X) {
    constexpr int BM = 128, BN = 128, BK = 16;
    __shared__ float As[BK][BM];
    __shared__ float Bs[BK][BN];

    const int tid = threadIdx.x;
    const int m0  = blockIdx.y * BM;
    const int n0  = blockIdx.x * BN;
    const int tx  = tid & 15;        // n-group 0..15
    const int ty  = tid >> 4;        // m-group 0..15
    const int lr  = tid >> 2;        // 0..63 (load row)
    const int lc  = (tid & 3) * 4;   // 0,4,8,12 (load col)

    float acc[8][8];
    #pragma unroll
    for (int i = 0; i < 8; i++)
        #pragma unroll
        for (int j = 0; j < 8; j++) acc[i][j] = 0.0f;

    const float* Ap = A + (size_t)m0 * KD;
    const float* Wp = W + (size_t)n0 * KD;

    for (int k0 = 0; k0 < KD; k0 += BK) {
        float4 a0 = *(const float4*)(Ap + (size_t)(lr     )*KD + k0 + lc);
        float4 a1 = *(const float4*)(Ap + (size_t)(lr + 64)*KD + k0 + lc);
        float4 b0 = *(const float4*)(Wp + (size_t)(lr     )*KD + k0 + lc);
        float4 b1 = *(const float4*)(Wp + (size_t)(lr + 64)*KD + k0 + lc);
        __syncthreads();   // previous tile fully consumed
        As[lc+0][lr] = a0.x; As[lc+1][lr] = a0.y; As[lc+2][lr] = a0.z; As[lc+3][lr] = a0.w;
        As[lc+0][lr+64] = a1.x; As[lc+1][lr+64] = a1.y; As[lc+2][lr+64] = a1.z; As[lc+3][lr+64] = a1.w;
        Bs[lc+0][lr] = b0.x; Bs[lc+1][lr] = b0.y; Bs[lc+2][lr] = b0.z; Bs[lc+3][lr] = b0.w;
        Bs[lc+0][lr+64] = b1.x; Bs[lc+1][lr+64] = b1.y; Bs[lc+2][lr+64] = b1.z; Bs[lc+3][lr+64] = b1.w;
        __syncthreads();

        #pragma unroll
        for (int kk = 0; kk < BK; kk++) {
            float a[8], b[8];
            *(float4*)(a    ) = *(const float4*)&As[kk][ty*4     ];
            *(float4*)(a + 4) = *(const float4*)&As[kk][ty*4 + 64];
            *(float4*)(b    ) = *(const float4*)&Bs[kk][tx*4     ];
            *(float4*)(b + 4) = *(const float4*)&Bs[kk][tx*4 + 64];
            #pragma unroll
            for (int i = 0; i < 8; i++)
                #pragma unroll
                for (int j = 0; j < 8; j++)
                    acc[i][j] = fmaf(a[i], b[j], acc[i][j]);
        }
    }

    // epilogue: EPI=0 plain store; EPI=1: out = acc + D[n]*X[m][n]
    float4 d0, d1;
    if (EPI == 1) {
        d0 = *(const float4*)(Dv + n0 + tx*4);
        d1 = *(const float4*)(Dv + n0 + tx*4 + 64);
    }
    #pragma unroll
    for (int i = 0; i < 8; i++) {
        int m = m0 + ((i < 4) ? (ty*4 + i) : (64 + ty*4 + i - 4));
        size_t base = (size_t)m * ND + n0;
        float4 v0 = make_float4(acc[i][0], acc[i][1], acc[i][2], acc[i][3]);
        float4 v1 = make_float4(acc[i][4], acc[i][5], acc[i][6], acc[i][7]);
        if (EPI == 1) {
            float4 x0 = *(const float4*)(X + base + tx*4);
            float4 x1 = *(const float4*)(X + base + tx*4 + 64);
            v0.x = fmaf(d0.x, x0.x, v0.x); v0.y = fmaf(d0.y, x0.y, v0.y);
            v0.z = fmaf(d0.z, x0.z, v0.z); v0.w = fmaf(d0.w, x0.w, v0.w);
            v1.x = fmaf(d1.x, x1.x, v1.x); v1.y = fmaf(d1.y, x1.y, v1.y);
            v1.z = fmaf(d1.z, x1.z, v1.z); v1.w = fmaf(d1.w, x1.w, v1.w);
        }
        *(float4*)(out + base + tx*4     ) = v0;
        *(float4*)(out + base + tx*4 + 64) = v1;
    }
}

// ---------------- scan kernels ----------------
// Pass A: chunk-final states (zero initial state per chunk)
__global__ void scan_carry() {
    int b = blockIdx.x / NCH;
    int c = blockIdx.x % NCH;
    int p = threadIdx.x;
    float2 lam = g_lambda[p];
    float2 s = make_float2(0.f, 0.f);
    const float2* bu = g_Bu + ((size_t)b*LSEQ + (size_t)c*LC)*PDIM + p;
    #pragma unroll 4
    for (int t = 0; t < LC; t++) {
        float2 u = bu[(size_t)t*PDIM];
        s = cfma(lam, s, u);
    }
    g_carry[((size_t)b*NCH + c)*PDIM + p] = s;
}

// Prefix over chunks: carry_in[c] = lam^LC * carry_in[c-1] (folded) ...
__global__ void scan_combine() {
    int b = blockIdx.x;
    int p = threadIdx.x;
    float2 Lp = g_lampow[p];
    float2 s = make_float2(0.f, 0.f);
    for (int c = 0; c < NCH; c++) {
        size_t idx = ((size_t)b*NCH + c)*PDIM + p;
        g_carry_in[idx] = s;
        float2 f = g_carry[idx];
        s = cfma(Lp, s, f);
    }
}

// Pass B: full scan with correct incoming carry, in place
__global__ void scan_apply() {
    int b = blockIdx.x / NCH;
    int c = blockIdx.x % NCH;
    int p = threadIdx.x;
    float2 lam = g_lambda[p];
    float2 s = g_carry_in[((size_t)b*NCH + c)*PDIM + p];
    float2* bu = g_Bu + ((size_t)b*LSEQ + (size_t)c*LC)*PDIM + p;
    #pragma unroll 4
    for (int t = 0; t < LC; t++) {
        float2 u = bu[(size_t)t*PDIM];
        s = cfma(lam, s, u);
        bu[(size_t)t*PDIM] = s;
    }
}

// ---------------- launch ----------------
extern "C" void kernel_launch(void* const* d_in, const int* in_sizes, int n_in,
                              void* d_out, int out_size) {
    const float* x     = (const float*)d_in[0];
    const float* Lre   = (const float*)d_in[1];
    const float* Lim   = (const float*)d_in[2];
    const float* Bm    = (const float*)d_in[3];
    const float* Cm    = (const float*)d_in[4];
    const float* Dv    = (const float*)d_in[5];
    const float* lstep = (const float*)d_in[6];
    float* y = (float*)d_out;

    void *bu_p, *w1_p, *w2_p;
    cudaGetSymbolAddress(&bu_p, g_Bu);
    cudaGetSymbolAddress(&w1_p, g_W1);
    cudaGetSymbolAddress(&w2_p, g_W2);

    prep_params<<<1, PDIM>>>(Lre, Lim, lstep);
    prep_w1<<<(PDIM*HDIM)/256, 256>>>(Bm);
    prep_w2<<<(HDIM*PDIM)/256, 256>>>(Cm);

    dim3 gg(ND/128, MROWS/128);
    // GEMM1: Bu = X @ W1^T   (out interleaved complex -> g_Bu)
    sgemm<0><<<gg, 256>>>(x, (const float*)w1_p, (float*)bu_p, nullptr, nullptr);

    // chunked linear scan over L (in place in g_Bu)
    scan_carry  <<<BSZ*NCH, PDIM>>>();
    scan_combine<<<BSZ,     PDIM>>>();
    scan_apply  <<<BSZ*NCH, PDIM>>>();

    // GEMM2: y = xs @ W2^T + D*x
    sgemm<1><<<gg, 256>>>((const float*)bu_p, (const float*)w2_p, y, Dv, x);
}

// round 7
// speedup vs baseline: 1.8153x; 1.8153x over previous
#include <cuda_runtime.h>
#include <cuda_bf16.h>
#include <math.h>
#include <stdint.h>

// Problem shapes (fixed by the dataset)
#define BSZ   8
#define LSEQ  4096
#define HDIM  512
#define PDIM  256
#define MROWS (BSZ*LSEQ)     // 32768
#define KD    512            // inner dim for both GEMMs
#define ND    512            // outer dim for both GEMMs
#define LC    64             // scan chunk length
#define NCH   (LSEQ/LC)      // 64 chunks per sequence

// GEMM tiling (mma.sync path)
#define BM 128
#define BN 64
#define BK 32
#define NK (KD/BK)           // 16 k-steps
#define STAGES 3

// smem layout (per stage), 80-byte padded rows (32 bf16 data + 8 pad)
#define ROWB 80
#define OFF_AHI 0
#define OFF_ALO (128*ROWB)              // 10240
#define OFF_WHI (2*128*ROWB)            // 20480
#define OFF_WLO (2*128*ROWB + 64*ROWB)  // 25600
#define STAGE_BYTES (2*128*ROWB + 2*64*ROWB)  // 30720
#define SMEM_TOTAL (STAGES*STAGE_BYTES)       // 92160

// ---------------- device scratch ----------------
__device__ float2        g_Bu[(size_t)MROWS * PDIM];       // 64 MB (GEMM1 out, fp32)
__device__ __nv_bfloat16 g_Xhi[(size_t)MROWS * KD];        // 32 MB
__device__ __nv_bfloat16 g_Xlo[(size_t)MROWS * KD];        // 32 MB
__device__ __nv_bfloat16 g_A2hi[(size_t)MROWS * KD];       // 32 MB (xs split)
__device__ __nv_bfloat16 g_A2lo[(size_t)MROWS * KD];       // 32 MB
__device__ __nv_bfloat16 g_W1hi[ND * KD], g_W1lo[ND * KD];
__device__ __nv_bfloat16 g_W2hi[HDIM * KD], g_W2lo[HDIM * KD];
__device__ float2 g_lambda[PDIM];
__device__ float2 g_lampow[PDIM];
__device__ float2 g_f[PDIM];
__device__ float2 g_carry[BSZ * NCH * PDIM];
__device__ float2 g_carry_in[BSZ * NCH * PDIM];

// ---------------- PTX helpers ----------------
__device__ __forceinline__ uint32_t smem_to_u32(const void* p) {
    uint32_t a;
    asm("{ .reg .u64 t; cvta.to.shared.u64 t, %1; cvt.u32.u64 %0, t; }" : "=r"(a) : "l"(p));
    return a;
}
__device__ __forceinline__ void cp_async16(uint32_t saddr, const void* gaddr) {
    asm volatile("cp.async.cg.shared.global [%0], [%1], 16;" :: "r"(saddr), "l"(gaddr));
}
#define CP_COMMIT() asm volatile("cp.async.commit_group;" ::: "memory")
#define CP_WAIT(n)  asm volatile("cp.async.wait_group %0;" :: "n"(n) : "memory")

__device__ __forceinline__ void ldsm_x4(uint32_t* r, uint32_t addr) {
    asm volatile("ldmatrix.sync.aligned.m8n8.x4.shared.b16 {%0,%1,%2,%3}, [%4];"
        : "=r"(r[0]), "=r"(r[1]), "=r"(r[2]), "=r"(r[3]) : "r"(addr));
}
__device__ __forceinline__ void mma_bf16(float* d, const uint32_t* a, uint32_t b0, uint32_t b1) {
    asm volatile(
        "mma.sync.aligned.m16n8k16.row.col.f32.bf16.bf16.f32 "
        "{%0,%1,%2,%3}, {%4,%5,%6,%7}, {%8,%9}, {%0,%1,%2,%3};"
        : "+f"(d[0]), "+f"(d[1]), "+f"(d[2]), "+f"(d[3])
        : "r"(a[0]), "r"(a[1]), "r"(a[2]), "r"(a[3]), "r"(b0), "r"(b1));
}

// ---------------- small helpers ----------------
__device__ __forceinline__ float2 cfma(float2 l, float2 s, float2 u) {
    float2 r;
    r.x = fmaf(l.x, s.x, fmaf(-l.y, s.y, u.x));
    r.y = fmaf(l.x, s.y, fmaf( l.y, s.x, u.y));
    return r;
}
__device__ __forceinline__ void split_bf16(float v, __nv_bfloat16& hi, __nv_bfloat16& lo) {
    hi = __float2bfloat16(v);
    lo = __float2bfloat16(v - __bfloat162float(hi));
}

// ---------------- precompute kernels ----------------
__global__ void prep_params(const float* __restrict__ Lre,
                            const float* __restrict__ Lim,
                            const float* __restrict__ lstep) {
    int p = threadIdx.x;
    float step = expf(lstep[p]);
    float ar = Lre[p] * step;
    float ai = Lim[p] * step;
    double mag = exp((double)ar);
    float2 lam;
    lam.x = (float)(mag * cos((double)ai));
    lam.y = (float)(mag * sin((double)ai));
    g_lambda[p] = lam;
    double zr = lam.x, zi = lam.y;
    #pragma unroll
    for (int i = 0; i < 6; i++) {  // lam^64
        double nr = zr*zr - zi*zi, ni = 2.0*zr*zi;
        zr = nr; zi = ni;
    }
    g_lampow[p] = make_float2((float)zr, (float)zi);
    float lr = Lre[p], li = Lim[p];
    float nr = lam.x - 1.0f, ni = lam.y;
    float den = lr*lr + li*li;
    g_f[p] = make_float2((nr*lr + ni*li)/den, (ni*lr - nr*li)/den);
}

__global__ void prep_w1(const float* __restrict__ Bm) {  // B: (P,H,2)
    int idx = blockIdx.x * blockDim.x + threadIdx.x;     // over P*H
    int p = idx / HDIM, h = idx % HDIM;
    float2 f = g_f[p];
    float b0 = Bm[(size_t)(p*HDIM + h)*2 + 0];
    float b1 = Bm[(size_t)(p*HDIM + h)*2 + 1];
    float re = f.x*b0 - f.y*b1;
    float im = f.x*b1 + f.y*b0;
    __nv_bfloat16 hi, lo;
    split_bf16(re, hi, lo);
    g_W1hi[(size_t)(2*p)*KD + h] = hi;  g_W1lo[(size_t)(2*p)*KD + h] = lo;
    split_bf16(im, hi, lo);
    g_W1hi[(size_t)(2*p+1)*KD + h] = hi;  g_W1lo[(size_t)(2*p+1)*KD + h] = lo;
}

__global__ void prep_w2(const float* __restrict__ Cm) {  // C: (H,P,2)
    int idx = blockIdx.x * blockDim.x + threadIdx.x;     // over H*P
    int h = idx / PDIM, p = idx % PDIM;
    float cre =  2.0f * Cm[(size_t)(h*PDIM + p)*2 + 0];
    float cim = -2.0f * Cm[(size_t)(h*PDIM + p)*2 + 1];
    __nv_bfloat16 hi, lo;
    split_bf16(cre, hi, lo);
    g_W2hi[(size_t)h*KD + 2*p] = hi;  g_W2lo[(size_t)h*KD + 2*p] = lo;
    split_bf16(cim, hi, lo);
    g_W2hi[(size_t)h*KD + 2*p+1] = hi;  g_W2lo[(size_t)h*KD + 2*p+1] = lo;
}

__global__ void conv_x(const float* __restrict__ x) {
    size_t i = ((size_t)blockIdx.x * blockDim.x + threadIdx.x) * 4;
    float4 v = *(const float4*)(x + i);
    __nv_bfloat16 h0,l0,h1,l1,h2,l2,h3,l3;
    split_bf16(v.x, h0, l0); split_bf16(v.y, h1, l1);
    split_bf16(v.z, h2, l2); split_bf16(v.w, h3, l3);
    __nv_bfloat162 hh0; hh0.x = h0; hh0.y = h1;
    __nv_bfloat162 hh1; hh1.x = h2; hh1.y = h3;
    __nv_bfloat162 ll0; ll0.x = l0; ll0.y = l1;
    __nv_bfloat162 ll1; ll1.x = l2; ll1.y = l3;
    *(__nv_bfloat162*)(g_Xhi + i)     = hh0;
    *(__nv_bfloat162*)(g_Xhi + i + 2) = hh1;
    *(__nv_bfloat162*)(g_Xlo + i)     = ll0;
    *(__nv_bfloat162*)(g_Xlo + i + 2) = ll1;
}

// ---------------- mma.sync split-bf16 GEMM ----------------
// out[m][n] = sum_k A[m][k]*W[n][k]; A,W given as bf16 hi/lo (K-major, stride KD)
template<int EPI>
__global__ __launch_bounds__(256)
void gemm_mma(const __nv_bfloat16* __restrict__ Ahi, const __nv_bfloat16* __restrict__ Alo,
              const __nv_bfloat16* __restrict__ Whi, const __nv_bfloat16* __restrict__ Wlo,
              float* __restrict__ out, const float* __restrict__ Dv,
              const float* __restrict__ X) {
    extern __shared__ char smem[];
    const uint32_t sb = smem_to_u32(smem);
    const int tid  = threadIdx.x;
    const int wid  = tid >> 5;
    const int lane = tid & 31;
    const int m0 = blockIdx.y * BM;
    const int n0 = blockIdx.x * BN;
    const int wm = wid & 3;          // m warp 0..3 (32 rows each)
    const int wn = wid >> 2;         // n warp 0..1 (32 cols each)

    // cp.async loader for one stage
    auto load_stage = [&](int s, int k0) {
        uint32_t st = sb + s * STAGE_BYTES;
        #pragma unroll
        for (int i = 0; i < 2; i++) {
            int task = tid + i * 256;          // 0..511
            int row = task >> 2, ch = task & 3;
            uint32_t so = (uint32_t)(row * ROWB + ch * 16);
            size_t g = (size_t)(m0 + row) * KD + k0 + ch * 8;
            cp_async16(st + OFF_AHI + so, Ahi + g);
            cp_async16(st + OFF_ALO + so, Alo + g);
        }
        {
            int row = tid >> 2, ch = tid & 3;  // 64 rows x 4 chunks = 256
            uint32_t so = (uint32_t)(row * ROWB + ch * 16);
            size_t g = (size_t)(n0 + row) * KD + k0 + ch * 8;
            cp_async16(st + OFF_WHI + so, Whi + g);
            cp_async16(st + OFF_WLO + so, Wlo + g);
        }
    };

    float acc[2][4][4];
    #pragma unroll
    for (int i = 0; i < 2; i++)
        #pragma unroll
        for (int j = 0; j < 4; j++)
            #pragma unroll
            for (int q = 0; q < 4; q++) acc[i][j][q] = 0.0f;

    load_stage(0, 0);  CP_COMMIT();
    load_stage(1, BK); CP_COMMIT();

    // ldmatrix lane addressing offsets
    const uint32_t lrow16 = (uint32_t)(lane & 15);       // row within 16
    const uint32_t lchunk = (uint32_t)((lane >> 4) << 4); // 0 or 16 bytes

    for (int k = 0; k < NK; k++) {
        CP_WAIT(1);
        __syncthreads();
        if (k + 2 < NK) load_stage((k + 2) % STAGES, (k + 2) * BK);
        CP_COMMIT();

        const uint32_t st = sb + (k % STAGES) * STAGE_BYTES;

        uint32_t ahi[2][2][4], alo[2][2][4];   // [mi][kh][4]
        uint32_t bhi[2][2][4], blo[2][2][4];   // [ng][kh][4]
        #pragma unroll
        for (int mi = 0; mi < 2; mi++) {
            uint32_t rowoff = (uint32_t)((wm * 32 + mi * 16) + lrow16) * ROWB;
            #pragma unroll
            for (int kh = 0; kh < 2; kh++) {
                uint32_t co = (uint32_t)(kh * 32) + lchunk;
                ldsm_x4(ahi[mi][kh], st + OFF_AHI + rowoff + co);
                ldsm_x4(alo[mi][kh], st + OFF_ALO + rowoff + co);
            }
        }
        #pragma unroll
        for (int ng = 0; ng < 2; ng++) {
            uint32_t rowoff = (uint32_t)((wn * 32 + ng * 16) + lrow16) * ROWB;
            #pragma unroll
            for (int kh = 0; kh < 2; kh++) {
                uint32_t co = (uint32_t)(kh * 32) + lchunk;
                ldsm_x4(bhi[ng][kh], st + OFF_WHI + rowoff + co);
                ldsm_x4(blo[ng][kh], st + OFF_WLO + rowoff + co);
            }
        }

        #pragma unroll
        for (int mi = 0; mi < 2; mi++) {
            #pragma unroll
            for (int j = 0; j < 4; j++) {
                const int ng = j >> 1, h = j & 1;
                #pragma unroll
                for (int kh = 0; kh < 2; kh++) {
                    mma_bf16(acc[mi][j], ahi[mi][kh], bhi[ng][kh][h], bhi[ng][kh][h + 2]);
                    mma_bf16(acc[mi][j], ahi[mi][kh], blo[ng][kh][h], blo[ng][kh][h + 2]);
                    mma_bf16(acc[mi][j], alo[mi][kh], bhi[ng][kh][h], bhi[ng][kh][h + 2]);
                }
            }
        }
        __syncthreads();
    }

    // epilogue: d-frag mapping: d0/d1 -> (row=l>>2, col=(l&3)*2 +0/1), d2/d3 -> row+8
    #pragma unroll
    for (int mi = 0; mi < 2; mi++) {
        #pragma unroll
        for (int j = 0; j < 4; j++) {
            int r = m0 + wm * 32 + mi * 16 + (lane >> 2);
            int c = n0 + wn * 32 + j * 8 + (lane & 3) * 2;
            size_t o0 = (size_t)r * ND + c;
            size_t o1 = (size_t)(r + 8) * ND + c;
            float2 v0; v0.x = acc[mi][j][0]; v0.y = acc[mi][j][1];
            float2 v1; v1.x = acc[mi][j][2]; v1.y = acc[mi][j][3];
            if (EPI == 1) {
                float2 dv = *(const float2*)(Dv + c);
                float2 x0 = *(const float2*)(X + o0);
                float2 x1 = *(const float2*)(X + o1);
                v0.x = fmaf(dv.x, x0.x, v0.x); v0.y = fmaf(dv.y, x0.y, v0.y);
                v1.x = fmaf(dv.x, x1.x, v1.x); v1.y = fmaf(dv.y, x1.y, v1.y);
            }
            *(float2*)(out + o0) = v0;
            *(float2*)(out + o1) = v1;
        }
    }
}

// ---------------- scan kernels ----------------
__global__ void scan_carry() {
    int b = blockIdx.x / NCH;
    int c = blockIdx.x % NCH;
    int p = threadIdx.x;
    float2 lam = g_lambda[p];
    float2 s = make_float2(0.f, 0.f);
    const float2* bu = g_Bu + ((size_t)b*LSEQ + (size_t)c*LC)*PDIM + p;
    #pragma unroll 4
    for (int t = 0; t < LC; t++) {
        float2 u = bu[(size_t)t*PDIM];
        s = cfma(lam, s, u);
    }
    g_carry[((size_t)b*NCH + c)*PDIM + p] = s;
}

__global__ void scan_combine() {
    int b = blockIdx.x;
    int p = threadIdx.x;
    float2 Lp = g_lampow[p];
    float2 s = make_float2(0.f, 0.f);
    for (int c = 0; c < NCH; c++) {
        size_t idx = ((size_t)b*NCH + c)*PDIM + p;
        g_carry_in[idx] = s;
        float2 f = g_carry[idx];
        s = cfma(Lp, s, f);
    }
}

// full scan with incoming carry; write bf16 hi/lo split of xs for GEMM2
__global__ void scan_apply() {
    int b = blockIdx.x / NCH;
    int c = blockIdx.x % NCH;
    int p = threadIdx.x;
    float2 lam = g_lambda[p];
    float2 s = g_carry_in[((size_t)b*NCH + c)*PDIM + p];
    size_t row0 = (size_t)b*LSEQ + (size_t)c*LC;
    const float2* bu = g_Bu + row0*PDIM + p;
    __nv_bfloat162* outh = (__nv_bfloat162*)g_A2hi + row0*PDIM + p;
    __nv_bfloat162* outl = (__nv_bfloat162*)g_A2lo + row0*PDIM + p;
    #pragma unroll 4
    for (int t = 0; t < LC; t++) {
        float2 u = bu[(size_t)t*PDIM];
        s = cfma(lam, s, u);
        __nv_bfloat16 hr, lr, hi, li;
        split_bf16(s.x, hr, lr);
        split_bf16(s.y, hi, li);
        __nv_bfloat162 vh; vh.x = hr; vh.y = hi;
        __nv_bfloat162 vl; vl.x = lr; vl.y = li;
        outh[(size_t)t*PDIM] = vh;
        outl[(size_t)t*PDIM] = vl;
    }
}

// ---------------- launch ----------------
extern "C" void kernel_launch(void* const* d_in, const int* in_sizes, int n_in,
                              void* d_out, int out_size) {
    const float* x     = (const float*)d_in[0];
    const float* Lre   = (const float*)d_in[1];
    const float* Lim   = (const float*)d_in[2];
    const float* Bm    = (const float*)d_in[3];
    const float* Cm    = (const float*)d_in[4];
    const float* Dv    = (const float*)d_in[5];
    const float* lstep = (const float*)d_in[6];
    float* y = (float*)d_out;

    void *bu_p, *xhi_p, *xlo_p, *a2hi_p, *a2lo_p, *w1hi_p, *w1lo_p, *w2hi_p, *w2lo_p;
    cudaGetSymbolAddress(&bu_p,   g_Bu);
    cudaGetSymbolAddress(&xhi_p,  g_Xhi);
    cudaGetSymbolAddress(&xlo_p,  g_Xlo);
    cudaGetSymbolAddress(&a2hi_p, g_A2hi);
    cudaGetSymbolAddress(&a2lo_p, g_A2lo);
    cudaGetSymbolAddress(&w1hi_p, g_W1hi);
    cudaGetSymbolAddress(&w1lo_p, g_W1lo);
    cudaGetSymbolAddress(&w2hi_p, g_W2hi);
    cudaGetSymbolAddress(&w2lo_p, g_W2lo);

    cudaFuncSetAttribute(gemm_mma<0>, cudaFuncAttributeMaxDynamicSharedMemorySize, SMEM_TOTAL);
    cudaFuncSetAttribute(gemm_mma<1>, cudaFuncAttributeMaxDynamicSharedMemorySize, SMEM_TOTAL);

    prep_params<<<1, PDIM>>>(Lre, Lim, lstep);
    prep_w1<<<(PDIM*HDIM)/256, 256>>>(Bm);
    prep_w2<<<(HDIM*PDIM)/256, 256>>>(Cm);
    conv_x<<<(size_t)MROWS*KD/4/256, 256>>>(x);

    dim3 gg(ND/BN, MROWS/BM);  // (8, 256)
    gemm_mma<0><<<gg, 256, SMEM_TOTAL>>>((const __nv_bfloat16*)xhi_p, (const __nv_bfloat16*)xlo_p,
                                         (const __nv_bfloat16*)w1hi_p, (const __nv_bfloat16*)w1lo_p,
                                         (float*)bu_p, nullptr, nullptr);

    scan_carry  <<<BSZ*NCH, PDIM>>>();
    scan_combine<<<BSZ,     PDIM>>>();
    scan_apply  <<<BSZ*NCH, PDIM>>>();

    gemm_mma<1><<<gg, 256, SMEM_TOTAL>>>((const __nv_bfloat16*)a2hi_p, (const __nv_bfloat16*)a2lo_p,
                                         (const __nv_bfloat16*)w2hi_p, (const __nv_bfloat16*)w2lo_p,
                                         y, Dv, x);
}